// round 7
// baseline (speedup 1.0000x reference)
#include <cuda_runtime.h>

// Problem dims (fixed by the reference setup_inputs)
#define B_    256
#define F_    300
#define JC_   1600
#define NC_   60
#define J4_   (JC_ / 4)    // 400 float4 per frame
#define CHUNK 30           // frames per pooling block
#define NCH   (F_ / CHUNK) // 10 chunks
#define ROWS_PER_FC 2      // batch rows per FC block
#define FC_BLOCKS (B_ / ROWS_PER_FC) // 128
#define NGRP  32           // j-groups in fc phase B
#define NQ    (NC_ / 4)    // 15 n-quads

// Chunk partial sums [B, NCH, J4] (device scratch: allocation-free)
__device__ float4 g_part[(size_t)B_ * NCH * J4_];

// ---------------------------------------------------------------------------
// Kernel 1: partial frame sums. grid = (B, NCH), block = 400. (proven, ~floor)
// ---------------------------------------------------------------------------
__global__ __launch_bounds__(J4_) void pool_part_kernel(
    const float* __restrict__ x,       // [B, F, JC]
    const int*   __restrict__ lengths) // [B]
{
    const int b  = blockIdx.x;
    const int c  = blockIdx.y;
    const int j4 = threadIdx.x;

    const int len = lengths[b];
    const int f0  = c * CHUNK;
    if (f0 >= len) return;
    const int f1  = min(f0 + CHUNK, len);

    const float4* __restrict__ xb =
        reinterpret_cast<const float4*>(x + (size_t)b * F_ * JC_);

    float ax = 0.f, ay = 0.f, az = 0.f, aw = 0.f;
    int f = f0;
    for (; f + 4 <= f1; f += 4) {
        float4 v0 = __ldcs(&xb[(size_t)(f + 0) * J4_ + j4]);
        float4 v1 = __ldcs(&xb[(size_t)(f + 1) * J4_ + j4]);
        float4 v2 = __ldcs(&xb[(size_t)(f + 2) * J4_ + j4]);
        float4 v3 = __ldcs(&xb[(size_t)(f + 3) * J4_ + j4]);
        ax += v0.x + v1.x + v2.x + v3.x;
        ay += v0.y + v1.y + v2.y + v3.y;
        az += v0.z + v1.z + v2.z + v3.z;
        aw += v0.w + v1.w + v2.w + v3.w;
    }
    for (; f < f1; f++) {
        float4 v = __ldcs(&xb[(size_t)f * J4_ + j4]);
        ax += v.x; ay += v.y; az += v.z; aw += v.w;
    }
    g_part[((size_t)b * NCH + c) * J4_ + j4] = make_float4(ax, ay, az, aw);
}

// ---------------------------------------------------------------------------
// Kernel 2: fused reduce + mean + edge case + FC.
// grid = 128 blocks x 2 batch rows, block = 512.
// Phase A: fully-unrolled PREDICATED reads of all 10 chunk partials
//          (10 independent LDGs in flight -> one DRAM latency, not ten).
// Phase B: thread (g = t>>4, q = t&15, q<15): group g owns j = k*32+g,
//          loads W4[j*15+q] (per-warp: 2 consecutive j-rows -> coalesced),
//          50 iterations x 8 independent FMA chains (2 rows x float4).
// Phase C: smem combine of 32 group partials + bias.
// ---------------------------------------------------------------------------
__global__ __launch_bounds__(512) void fc_kernel(
    const float* __restrict__ x,       // [B, F, JC] (len<=1 edge case)
    const int*   __restrict__ lengths, // [B]
    const float* __restrict__ W,       // [JC, NC] row-major
    const float* __restrict__ bias,    // [NC]
    float*       __restrict__ out)     // [B, NC]
{
    __shared__ float sp[ROWS_PER_FC][JC_];            // 12.8 KB pooled rows
    __shared__ float red[ROWS_PER_FC][NGRP][NC_];     // 15.4 KB group partials

    const int b0 = blockIdx.x * ROWS_PER_FC;
    const int t  = threadIdx.x;

    // ---- Phase A: pooled rows into shared (predicated, fully unrolled) ----
    for (int rc = t; rc < ROWS_PER_FC * J4_; rc += 512) {
        const int r  = rc / J4_;
        const int j4 = rc - r * J4_;
        const int b  = b0 + r;
        const int len = lengths[b];
        float4 s;
        if (len <= 1) {
            s = reinterpret_cast<const float4*>(x + (size_t)b * F_ * JC_)[j4];
        } else {
            float ax = 0.f, ay = 0.f, az = 0.f, aw = 0.f;
            const float4* __restrict__ pb = &g_part[(size_t)b * NCH * J4_ + j4];
#pragma unroll
            for (int c = 0; c < NCH; c++) {
                if (c * CHUNK < len) {           // predicated; 10 independent loads
                    float4 v = pb[(size_t)c * J4_];
                    ax += v.x; ay += v.y; az += v.z; aw += v.w;
                }
            }
            const float inv = 1.0f / (float)len;
            s = make_float4(ax * inv, ay * inv, az * inv, aw * inv);
        }
        reinterpret_cast<float4*>(sp[r])[j4] = s;
    }
    __syncthreads();

    // ---- Phase B: 32 groups x 15 quads ----
    const int g = t >> 4;      // 0..31
    const int q = t & 15;      // 0..15 (15 idle)
    if (q < NQ) {
        const float4* __restrict__ W4 = reinterpret_cast<const float4*>(W); // [JC][15]
        float4 a0 = make_float4(0.f, 0.f, 0.f, 0.f);
        float4 a1 = a0;
#pragma unroll 5
        for (int k = 0; k < JC_ / NGRP; k++) {   // 50 iterations
            const int j = k * NGRP + g;
            const float4 wv = W4[(size_t)j * NQ + q];
            const float s0 = sp[0][j];
            const float s1 = sp[1][j];
            a0.x += s0 * wv.x; a0.y += s0 * wv.y; a0.z += s0 * wv.z; a0.w += s0 * wv.w;
            a1.x += s1 * wv.x; a1.y += s1 * wv.y; a1.z += s1 * wv.z; a1.w += s1 * wv.w;
        }
        const int n = 4 * q;
        red[0][g][n + 0] = a0.x; red[0][g][n + 1] = a0.y;
        red[0][g][n + 2] = a0.z; red[0][g][n + 3] = a0.w;
        red[1][g][n + 0] = a1.x; red[1][g][n + 1] = a1.y;
        red[1][g][n + 2] = a1.z; red[1][g][n + 3] = a1.w;
    }
    __syncthreads();

    // ---- Phase C: combine 32 group partials + bias, write out ----
    if (t < ROWS_PER_FC * NC_) {
        const int r  = t / NC_;
        const int nn = t - r * NC_;
        float acc = bias[nn];
#pragma unroll
        for (int gg = 0; gg < NGRP; gg++) acc += red[r][gg][nn];
        out[(size_t)(b0 + r) * NC_ + nn] = acc;
    }
}

extern "C" void kernel_launch(void* const* d_in, const int* in_sizes, int n_in,
                              void* d_out, int out_size)
{
    const float* x       = (const float*)d_in[0];
    const int*   lengths = (const int*)  d_in[1];
    const float* W       = (const float*)d_in[2];
    const float* bias    = (const float*)d_in[3];
    float*       out     = (float*)d_out;

    dim3 grid_pool(B_, NCH);
    pool_part_kernel<<<grid_pool, J4_>>>(x, lengths);
    fc_kernel<<<FC_BLOCKS, 512>>>(x, lengths, W, bias, out);
}

// round 8
// speedup vs baseline: 1.0180x; 1.0180x over previous
#include <cuda_runtime.h>

// Problem dims (fixed by the reference setup_inputs)
#define B_    256
#define F_    300
#define JC_   1600
#define NC_   60
#define J4_   (JC_ / 4)    // 400 float4 per frame
#define CHUNK 30           // frames per pooling block
#define NCH   (F_ / CHUNK) // 10 chunks
#define ROWS_PER_FC 2      // batch rows per FC block
#define FC_BLOCKS (B_ / ROWS_PER_FC) // 128
#define NGRP  32           // j-groups in fc phase B
#define NQ    (NC_ / 4)    // 15 n-quads

// Pooled (un-normalized) feature sums [B, JC] — 1.6 MB, built via red.global
__device__ float g_pooled[(size_t)B_ * JC_];

// ---------------------------------------------------------------------------
// Kernel 1: partial frame sums -> atomic accumulate into g_pooled.
// grid = (B, NCH), block = 400. x streamed with __ldcs.
// red.global.add.v4.f32: no-return vector reduction (sm_90+), spread addrs.
// ---------------------------------------------------------------------------
__global__ __launch_bounds__(J4_) void pool_part_kernel(
    const float* __restrict__ x,       // [B, F, JC]
    const int*   __restrict__ lengths) // [B]
{
    const int b  = blockIdx.x;
    const int c  = blockIdx.y;
    const int j4 = threadIdx.x;

    const int len = lengths[b];
    const int f0  = c * CHUNK;
    if (f0 >= len) return;
    const int f1  = min(f0 + CHUNK, len);

    const float4* __restrict__ xb =
        reinterpret_cast<const float4*>(x + (size_t)b * F_ * JC_);

    float ax = 0.f, ay = 0.f, az = 0.f, aw = 0.f;
    int f = f0;
    for (; f + 4 <= f1; f += 4) {
        float4 v0 = __ldcs(&xb[(size_t)(f + 0) * J4_ + j4]);
        float4 v1 = __ldcs(&xb[(size_t)(f + 1) * J4_ + j4]);
        float4 v2 = __ldcs(&xb[(size_t)(f + 2) * J4_ + j4]);
        float4 v3 = __ldcs(&xb[(size_t)(f + 3) * J4_ + j4]);
        ax += v0.x + v1.x + v2.x + v3.x;
        ay += v0.y + v1.y + v2.y + v3.y;
        az += v0.z + v1.z + v2.z + v3.z;
        aw += v0.w + v1.w + v2.w + v3.w;
    }
    for (; f < f1; f++) {
        float4 v = __ldcs(&xb[(size_t)f * J4_ + j4]);
        ax += v.x; ay += v.y; az += v.z; aw += v.w;
    }

    float* dst = g_pooled + (size_t)b * JC_ + j4 * 4;
    asm volatile("red.global.add.v4.f32 [%0], {%1, %2, %3, %4};"
                 :: "l"(dst), "f"(ax), "f"(ay), "f"(az), "f"(aw)
                 : "memory");
}

// ---------------------------------------------------------------------------
// Kernel 2: mean + edge case + FC.
// grid = 128 blocks x 2 batch rows, block = 512.
// Phase A: one L2-hit float4 load of g_pooled per element, scale by 1/len,
//          len<=1 -> frame 0 of x directly.
// Phase B: 32 j-groups x 15 n-quads, coalesced W float4 loads, 8 FMA chains.
// Phase C: smem combine + bias.
// ---------------------------------------------------------------------------
__global__ __launch_bounds__(512) void fc_kernel(
    const float* __restrict__ x,       // [B, F, JC] (len<=1 edge case)
    const int*   __restrict__ lengths, // [B]
    const float* __restrict__ W,       // [JC, NC] row-major
    const float* __restrict__ bias,    // [NC]
    float*       __restrict__ out)     // [B, NC]
{
    __shared__ float sp[ROWS_PER_FC][JC_];            // 12.8 KB pooled rows
    __shared__ float red_s[ROWS_PER_FC][NGRP][NC_];   // 15.4 KB group partials

    const int b0 = blockIdx.x * ROWS_PER_FC;
    const int t  = threadIdx.x;

    // ---- Phase A ----
    for (int rc = t; rc < ROWS_PER_FC * J4_; rc += 512) {
        const int r  = rc / J4_;
        const int j4 = rc - r * J4_;
        const int b  = b0 + r;
        const int len = lengths[b];
        float4 s;
        if (len <= 1) {
            s = reinterpret_cast<const float4*>(x + (size_t)b * F_ * JC_)[j4];
        } else {
            float4 v = reinterpret_cast<const float4*>(g_pooled)[(size_t)b * J4_ + j4];
            const float inv = 1.0f / (float)len;
            s = make_float4(v.x * inv, v.y * inv, v.z * inv, v.w * inv);
        }
        reinterpret_cast<float4*>(sp[r])[j4] = s;
    }
    __syncthreads();

    // ---- Phase B: 32 groups x 15 quads ----
    const int g = t >> 4;      // 0..31
    const int q = t & 15;      // 0..15 (15 idle)
    if (q < NQ) {
        const float4* __restrict__ W4 = reinterpret_cast<const float4*>(W); // [JC][15]
        float4 a0 = make_float4(0.f, 0.f, 0.f, 0.f);
        float4 a1 = a0;
#pragma unroll 5
        for (int k = 0; k < JC_ / NGRP; k++) {   // 50 iterations
            const int j = k * NGRP + g;
            const float4 wv = W4[(size_t)j * NQ + q];
            const float s0 = sp[0][j];
            const float s1 = sp[1][j];
            a0.x += s0 * wv.x; a0.y += s0 * wv.y; a0.z += s0 * wv.z; a0.w += s0 * wv.w;
            a1.x += s1 * wv.x; a1.y += s1 * wv.y; a1.z += s1 * wv.z; a1.w += s1 * wv.w;
        }
        const int n = 4 * q;
        red_s[0][g][n + 0] = a0.x; red_s[0][g][n + 1] = a0.y;
        red_s[0][g][n + 2] = a0.z; red_s[0][g][n + 3] = a0.w;
        red_s[1][g][n + 0] = a1.x; red_s[1][g][n + 1] = a1.y;
        red_s[1][g][n + 2] = a1.z; red_s[1][g][n + 3] = a1.w;
    }
    __syncthreads();

    // ---- Phase C: combine group partials + bias, write out ----
    if (t < ROWS_PER_FC * NC_) {
        const int r  = t / NC_;
        const int nn = t - r * NC_;
        float acc = bias[nn];
#pragma unroll
        for (int gg = 0; gg < NGRP; gg++) acc += red_s[r][gg][nn];
        out[(size_t)(b0 + r) * NC_ + nn] = acc;
    }
}

extern "C" void kernel_launch(void* const* d_in, const int* in_sizes, int n_in,
                              void* d_out, int out_size)
{
    const float* x       = (const float*)d_in[0];
    const int*   lengths = (const int*)  d_in[1];
    const float* W       = (const float*)d_in[2];
    const float* bias    = (const float*)d_in[3];
    float*       out     = (float*)d_out;

    // zero the accumulator (graph-capturable memset node; no allocation)
    void* pooled_ptr = nullptr;
    cudaGetSymbolAddress(&pooled_ptr, g_pooled);
    cudaMemsetAsync(pooled_ptr, 0, sizeof(float) * (size_t)B_ * JC_);

    dim3 grid_pool(B_, NCH);
    pool_part_kernel<<<grid_pool, J4_>>>(x, lengths);
    fc_kernel<<<FC_BLOCKS, 512>>>(x, lengths, W, bias, out);
}